// round 14
// baseline (speedup 1.0000x reference)
#include <cuda_runtime.h>
#include <cuda_bf16.h>
#include <cstdint>
#include <math.h>

#define N_NODES 128
#define F_DIM   128
#define H_DIM   64
#define C_OUT   40
#define BATCH   4096

// ===========================================================================
// Device globals (prep kernels fill these each launch)
// ===========================================================================
__device__ __align__(16) float g_Ahat[N_NODES * N_NODES];
__device__                float g_deg[N_NODES];
__device__ __align__(16) float g_A2[N_NODES * N_NODES];
// A2 in mma A-fragment layout: [p(2)][mtile(8)][s(8)][lane(32)] uint4
__device__ __align__(16) uint4 g_A2frag[4096];
// W in mma B-fragment layout: [s(8)][p(2)][j(4)][lane(32)] uint4
__device__ __align__(16) uint4 g_Wfrag[2048];

// ===========================================================================
// Helpers
// ===========================================================================
__device__ __forceinline__ unsigned smem_u32(const void* p) {
    unsigned a;
    asm("{ .reg .u64 t; cvta.to.shared.u64 t, %1; cvt.u32.u64 %0, t; }"
        : "=r"(a) : "l"(p));
    return a;
}

// packed bf16x2 convert: low half <- v0, high half <- v1
__device__ __forceinline__ unsigned cvt_bf2(float v0, float v1) {
    unsigned r;
    asm("cvt.rn.bf16x2.f32 %0, %1, %2;" : "=r"(r) : "f"(v1), "f"(v0));
    return r;
}
// split two floats into hi bf16x2 + residual-lo bf16x2
__device__ __forceinline__ void split2(float v0, float v1,
                                       unsigned& hi, unsigned& lo) {
    hi = cvt_bf2(v0, v1);
    float h0 = __uint_as_float(hi << 16);
    float h1 = __uint_as_float(hi & 0xffff0000u);
    lo = cvt_bf2(v0 - h0, v1 - h1);
}
// prep-side pack (p=0 hi, p=1 lo residual)
__device__ __forceinline__ unsigned bsplit_pack(float v0, float v1, int p) {
    __nv_bfloat16 h0 = __float2bfloat16(v0);
    __nv_bfloat16 h1 = __float2bfloat16(v1);
    if (p) {
        h0 = __float2bfloat16(v0 - __bfloat162float(h0));
        h1 = __float2bfloat16(v1 - __bfloat162float(h1));
    }
    return (unsigned)__bfloat16_as_ushort(h0) |
           ((unsigned)__bfloat16_as_ushort(h1) << 16);
}

__device__ __forceinline__ void mma_bf16(float* d, const unsigned* a,
                                         unsigned b0, unsigned b1) {
    asm volatile(
        "mma.sync.aligned.m16n8k16.row.col.f32.bf16.bf16.f32 "
        "{%0,%1,%2,%3}, {%4,%5,%6,%7}, {%8,%9}, {%0,%1,%2,%3};"
        : "+f"(d[0]), "+f"(d[1]), "+f"(d[2]), "+f"(d[3])
        : "r"(a[0]), "r"(a[1]), "r"(a[2]), "r"(a[3]), "r"(b0), "r"(b1));
}

#define LDM_X4(r, addr) \
    asm volatile("ldmatrix.sync.aligned.m8n8.x4.shared.b16 {%0,%1,%2,%3}, [%4];" \
        : "=r"((r)[0]), "=r"((r)[1]), "=r"((r)[2]), "=r"((r)[3]) : "r"(addr))
#define LDM_X4T(r, addr) \
    asm volatile("ldmatrix.sync.aligned.m8n8.x4.trans.shared.b16 {%0,%1,%2,%3}, [%4];" \
        : "=r"((r)[0]), "=r"((r)[1]), "=r"((r)[2]), "=r"((r)[3]) : "r"(addr))

// ===========================================================================
// Prep 1: Ahat = A_sym + I, degrees
// ===========================================================================
__global__ void build_Ahat(const float* __restrict__ edge_w) {
    __shared__ float red[4];
    int i = blockIdx.x, j = threadIdx.x;
    int a = i > j ? i : j;
    int b = i > j ? j : i;
    float v = edge_w[(a * (a + 1)) / 2 + b];
    if (i == j) v += 1.0f;
    g_Ahat[i * N_NODES + j] = v;
    float s = v;
#pragma unroll
    for (int o = 16; o > 0; o >>= 1) s += __shfl_xor_sync(0xffffffffu, s, o);
    if ((j & 31) == 0) red[j >> 5] = s;
    __syncthreads();
    if (j == 0) g_deg[i] = red[0] + red[1] + red[2] + red[3];
}

// ===========================================================================
// Prep 2: A2 = (D^-1/2 Ahat D^-1/2)^2 (fp32)
// ===========================================================================
__global__ void build_A2() {
    __shared__ float rowi[N_NODES];
    __shared__ float dinvS[N_NODES];
    int i = blockIdx.x, j = threadIdx.x;
    float dg = g_deg[j];
    float dj = (dg > 0.f) ? (1.0f / sqrtf(dg)) : 0.0f;
    dinvS[j] = dj;
    rowi[j] = g_Ahat[i * N_NODES + j] * dj * dj;
    __syncthreads();
    float s = 0.f;
    for (int k = 0; k < N_NODES; k++)
        s = fmaf(rowi[k], g_Ahat[k * N_NODES + j], s);
    g_A2[i * N_NODES + j] = s * dinvS[i] * dinvS[j];
}

// ===========================================================================
// Prep 3 (fused): A2 -> A-fragment layout (bf16 hi+lo);
//                 lin_w -> B-fragment layout (bf16 hi+lo).
// Blocks 0-15: A2frag (4096 uint4). Blocks 16-23: Wfrag (2048 uint4).
// ===========================================================================
__global__ void build_frags(const float* __restrict__ lin_w) {
    int bid = blockIdx.x;
    if (bid < 16) {
        int idx = bid * 256 + threadIdx.x;
        int l = idx & 31, s = (idx >> 5) & 7, w = (idx >> 8) & 7, p = idx >> 11;
        int r0 = 16 * w + (l >> 2);
        int k0 = 16 * s + 2 * (l & 3);
        const float* A = g_A2;
        uint4 r;
        r.x = bsplit_pack(A[r0 * 128 + k0],           A[r0 * 128 + k0 + 1],       p);
        r.y = bsplit_pack(A[(r0 + 8) * 128 + k0],     A[(r0 + 8) * 128 + k0 + 1], p);
        r.z = bsplit_pack(A[r0 * 128 + k0 + 8],       A[r0 * 128 + k0 + 9],       p);
        r.w = bsplit_pack(A[(r0 + 8) * 128 + k0 + 8], A[(r0 + 8) * 128 + k0 + 9], p);
        g_A2frag[idx] = r;
    } else {
        int idx = (bid - 16) * 256 + threadIdx.x;
        int l = idx & 31, j = (idx >> 5) & 3, p = (idx >> 7) & 1, s = idx >> 8;
        int n0 = 16 * j + (l >> 2);
        int n1 = n0 + 8;
        int k0 = 16 * s + 2 * (l & 3);
        const float* W = lin_w;
        uint4 r;
        r.x = bsplit_pack(W[k0 * 64 + n0],       W[(k0 + 1) * 64 + n0], p);
        r.y = bsplit_pack(W[(k0 + 8) * 64 + n0], W[(k0 + 9) * 64 + n0], p);
        r.z = bsplit_pack(W[k0 * 64 + n1],       W[(k0 + 1) * 64 + n1], p);
        r.w = bsplit_pack(W[(k0 + 8) * 64 + n1], W[(k0 + 9) * 64 + n1], p);
        g_Wfrag[idx] = r;
    }
}

// ===========================================================================
// Fused kernel: 1 batch/CTA, 256 threads, 3 CTAs/SM.
// bf16 3-phase split (hh + lh + hl): proven rel_err ~1.1e-4.
// K-split X staging: stage 64-feature halves into a reused buffer so smem
// drops to 74.75KB -> 3 CTAs/SM (vs 107.5KB / 2 CTAs in R8).
// Warp grid: wM = wid&3 (rows 32*wM..+31), wN = wid>>2 (cols 32*wN..+31).
// SMEM: Xhi [128][72]bf16 @0 (18432) | Xlo @18432 (18432) |
//   WY @36864 (36864): W-frags (32KB) during GEMM1, then Yhi/Ylo [128][72]bf16
//   pool/lb/cw @73728 (1024).  Total 74752.
// ===========================================================================
#define SM_XLO   18432
#define SM_WY    36864
#define SM_POOL  73728
#define SM_TOTAL 74752
#define XSTRIDE  144
#define YSTRIDE  144

__global__ void __launch_bounds__(256, 3) fused_mma(
    const float* __restrict__ x,
    const float* __restrict__ lin_b,
    const float* __restrict__ conv_w, const float* __restrict__ conv_b,
    const float* __restrict__ fc_w, const float* __restrict__ fc_b,
    float* __restrict__ out)
{
    extern __shared__ char sm[];
    const unsigned smb = smem_u32(sm);
    const int tid = threadIdx.x, wid = tid >> 5, lane = tid & 31;
    const int wM = wid & 3, wN = wid >> 2;
    const int b = blockIdx.x;

    float* pool = (float*)(sm + SM_POOL);
    float* lbS  = pool + 64;
    float* cwS  = pool + 128;
    if (tid < 64) { pool[tid] = __ldg(conv_b); lbS[tid] = __ldg(lin_b + tid); }
    if (tid < 128) cwS[tid] = __ldg(conv_w + tid);

    // ---- W fragments into smem (WY region; W live through all of GEMM1) ----
    {
        uint4* WFs = (uint4*)(sm + SM_WY);
#pragma unroll
        for (int i = 0; i < 8; i++) WFs[tid + i * 256] = g_Wfrag[tid + i * 256];
    }

    // ---- GEMM1: Y = X @ W, K-split into two 64-feature halves ----
    float acc[2][4][4];
#pragma unroll
    for (int m = 0; m < 2; m++)
#pragma unroll
        for (int t = 0; t < 4; t++)
#pragma unroll
            for (int q = 0; q < 4; q++) acc[m][t][q] = 0.f;

    const float4* X4 = (const float4*)(x + (size_t)b * (N_NODES * F_DIM));
    char* Xhi = sm;
    char* Xlo = sm + SM_XLO;
    const unsigned axh0 = smb + (32 * wM + (lane & 15)) * XSTRIDE + (lane >> 4) * 16;
    const unsigned axh1 = axh0 + 16 * XSTRIDE;
    const unsigned axl0 = axh0 + SM_XLO;
    const unsigned axl1 = axh1 + SM_XLO;
    const uint4* WFs = (const uint4*)(sm + SM_WY);

#pragma unroll
    for (int half = 0; half < 2; half++) {
        // stage this K-half of X (bf16 hi/lo split), coalesced
#pragma unroll
        for (int i = 0; i < 8; i++) {
            int idx = tid + i * 256;          // 2048 = 128 rows x 16 f4
            int n = idx >> 4, f4l = idx & 15;
            float4 v = X4[n * 32 + half * 16 + f4l];
            unsigned hw0, lw0, hw1, lw1;
            split2(v.x, v.y, hw0, lw0);
            split2(v.z, v.w, hw1, lw1);
            *(uint2*)(Xhi + n * XSTRIDE + f4l * 8) = make_uint2(hw0, hw1);
            *(uint2*)(Xlo + n * XSTRIDE + f4l * 8) = make_uint2(lw0, lw1);
        }
        __syncthreads();

#pragma unroll
        for (int sl = 0; sl < 4; sl++) {
            int s = 4 * half + sl;
            unsigned Ah0[4], Ah1[4], Al0[4], Al1[4];
            LDM_X4(Ah0, axh0 + sl * 32);
            LDM_X4(Ah1, axh1 + sl * 32);
            LDM_X4(Al0, axl0 + sl * 32);
            LDM_X4(Al1, axl1 + sl * 32);
            uint4 Bh0 = WFs[(8 * s + 2 * wN) * 32 + lane];
            uint4 Bh1 = WFs[(8 * s + 2 * wN + 1) * 32 + lane];
            uint4 Bl0 = WFs[(8 * s + 4 + 2 * wN) * 32 + lane];
            uint4 Bl1 = WFs[(8 * s + 4 + 2 * wN + 1) * 32 + lane];
            // hi*hi
            mma_bf16(acc[0][0], Ah0, Bh0.x, Bh0.y);
            mma_bf16(acc[0][1], Ah0, Bh0.z, Bh0.w);
            mma_bf16(acc[0][2], Ah0, Bh1.x, Bh1.y);
            mma_bf16(acc[0][3], Ah0, Bh1.z, Bh1.w);
            mma_bf16(acc[1][0], Ah1, Bh0.x, Bh0.y);
            mma_bf16(acc[1][1], Ah1, Bh0.z, Bh0.w);
            mma_bf16(acc[1][2], Ah1, Bh1.x, Bh1.y);
            mma_bf16(acc[1][3], Ah1, Bh1.z, Bh1.w);
            // lo*hi
            mma_bf16(acc[0][0], Al0, Bh0.x, Bh0.y);
            mma_bf16(acc[0][1], Al0, Bh0.z, Bh0.w);
            mma_bf16(acc[0][2], Al0, Bh1.x, Bh1.y);
            mma_bf16(acc[0][3], Al0, Bh1.z, Bh1.w);
            mma_bf16(acc[1][0], Al1, Bh0.x, Bh0.y);
            mma_bf16(acc[1][1], Al1, Bh0.z, Bh0.w);
            mma_bf16(acc[1][2], Al1, Bh1.x, Bh1.y);
            mma_bf16(acc[1][3], Al1, Bh1.z, Bh1.w);
            // hi*lo
            mma_bf16(acc[0][0], Ah0, Bl0.x, Bl0.y);
            mma_bf16(acc[0][1], Ah0, Bl0.z, Bl0.w);
            mma_bf16(acc[0][2], Ah0, Bl1.x, Bl1.y);
            mma_bf16(acc[0][3], Ah0, Bl1.z, Bl1.w);
            mma_bf16(acc[1][0], Ah1, Bl0.x, Bl0.y);
            mma_bf16(acc[1][1], Ah1, Bl0.z, Bl0.w);
            mma_bf16(acc[1][2], Ah1, Bl1.x, Bl1.y);
            mma_bf16(acc[1][3], Ah1, Bl1.z, Bl1.w);
        }
        __syncthreads();   // before restaging (half 0) / before Y store (half 1)
    }

    // ---- store Y split to smem over the W region ([node][h] row-major) ----
    {
        char* Yhi = sm + SM_WY;
        char* Ylo = Yhi + 18432;
        int r0 = 32 * wM + (lane >> 2);
        int c0 = 32 * wN + 2 * (lane & 3);
#pragma unroll
        for (int m = 0; m < 2; m++) {
            int r = r0 + 16 * m;
#pragma unroll
            for (int t = 0; t < 4; t++) {
                const float* a = acc[m][t];
                int cb = (c0 + 8 * t) * 2;
                unsigned h0, l0, h1, l1;
                split2(a[0], a[1], h0, l0);
                split2(a[2], a[3], h1, l1);
                *(unsigned*)(Yhi + r * YSTRIDE + cb)       = h0;
                *(unsigned*)(Yhi + (r + 8) * YSTRIDE + cb) = h1;
                *(unsigned*)(Ylo + r * YSTRIDE + cb)       = l0;
                *(unsigned*)(Ylo + (r + 8) * YSTRIDE + cb) = l1;
            }
        }
    }
    __syncthreads();

    // ---- GEMM2: Z = A2 @ Y  (A2 frags from L2, Y via ldmatrix.trans) ----
    float acc2[2][4][4];
#pragma unroll
    for (int m = 0; m < 2; m++)
#pragma unroll
        for (int t = 0; t < 4; t++)
#pragma unroll
            for (int q = 0; q < 4; q++) acc2[m][t][q] = 0.f;

    {
        unsigned ayh = smb + SM_WY + (lane & 15) * YSTRIDE + (lane >> 4) * 16;
        unsigned ayl = ayh + 18432;
#pragma unroll
        for (int s = 0; s < 8; s++) {
            uint4 vh0 = g_A2frag[((2 * wM) * 8 + s) * 32 + lane];
            uint4 vh1 = g_A2frag[((2 * wM + 1) * 8 + s) * 32 + lane];
            uint4 vl0 = g_A2frag[2048 + ((2 * wM) * 8 + s) * 32 + lane];
            uint4 vl1 = g_A2frag[2048 + ((2 * wM + 1) * 8 + s) * 32 + lane];
            unsigned ah0[4] = {vh0.x, vh0.y, vh0.z, vh0.w};
            unsigned ah1[4] = {vh1.x, vh1.y, vh1.z, vh1.w};
            unsigned al0[4] = {vl0.x, vl0.y, vl0.z, vl0.w};
            unsigned al1[4] = {vl1.x, vl1.y, vl1.z, vl1.w};
            unsigned Yh0[4], Yh1[4], Yl0[4], Yl1[4];
            unsigned yb = s * (16 * YSTRIDE);
            LDM_X4T(Yh0, ayh + yb + (2 * wN) * 32);
            LDM_X4T(Yh1, ayh + yb + (2 * wN + 1) * 32);
            LDM_X4T(Yl0, ayl + yb + (2 * wN) * 32);
            LDM_X4T(Yl1, ayl + yb + (2 * wN + 1) * 32);
            // hi*hi
            mma_bf16(acc2[0][0], ah0, Yh0[0], Yh0[1]);
            mma_bf16(acc2[0][1], ah0, Yh0[2], Yh0[3]);
            mma_bf16(acc2[0][2], ah0, Yh1[0], Yh1[1]);
            mma_bf16(acc2[0][3], ah0, Yh1[2], Yh1[3]);
            mma_bf16(acc2[1][0], ah1, Yh0[0], Yh0[1]);
            mma_bf16(acc2[1][1], ah1, Yh0[2], Yh0[3]);
            mma_bf16(acc2[1][2], ah1, Yh1[0], Yh1[1]);
            mma_bf16(acc2[1][3], ah1, Yh1[2], Yh1[3]);
            // lo*hi
            mma_bf16(acc2[0][0], al0, Yh0[0], Yh0[1]);
            mma_bf16(acc2[0][1], al0, Yh0[2], Yh0[3]);
            mma_bf16(acc2[0][2], al0, Yh1[0], Yh1[1]);
            mma_bf16(acc2[0][3], al0, Yh1[2], Yh1[3]);
            mma_bf16(acc2[1][0], al1, Yh0[0], Yh0[1]);
            mma_bf16(acc2[1][1], al1, Yh0[2], Yh0[3]);
            mma_bf16(acc2[1][2], al1, Yh1[0], Yh1[1]);
            mma_bf16(acc2[1][3], al1, Yh1[2], Yh1[3]);
            // hi*lo
            mma_bf16(acc2[0][0], ah0, Yl0[0], Yl0[1]);
            mma_bf16(acc2[0][1], ah0, Yl0[2], Yl0[3]);
            mma_bf16(acc2[0][2], ah0, Yl1[0], Yl1[1]);
            mma_bf16(acc2[0][3], ah0, Yl1[2], Yl1[3]);
            mma_bf16(acc2[1][0], ah1, Yl0[0], Yl0[1]);
            mma_bf16(acc2[1][1], ah1, Yl0[2], Yl0[3]);
            mma_bf16(acc2[1][2], ah1, Yl1[0], Yl1[1]);
            mma_bf16(acc2[1][3], ah1, Yl1[2], Yl1[3]);
        }
    }

    // ---- epilogue: relu(Z + lin_b) * conv_w, pool over nodes ----
    {
        int rb = 32 * wM + (lane >> 2);
        float cwA = cwS[rb],      cwB = cwS[rb + 8];
        float cwC = cwS[rb + 16], cwD = cwS[rb + 24];
#pragma unroll
        for (int t = 0; t < 4; t++) {
            int c0 = 32 * wN + 8 * t + 2 * (lane & 3);
            float b0v = lbS[c0], b1v = lbS[c0 + 1];
            float p0 = fmaxf(acc2[0][t][0] + b0v, 0.f) * cwA +
                       fmaxf(acc2[0][t][2] + b0v, 0.f) * cwB +
                       fmaxf(acc2[1][t][0] + b0v, 0.f) * cwC +
                       fmaxf(acc2[1][t][2] + b0v, 0.f) * cwD;
            float p1 = fmaxf(acc2[0][t][1] + b1v, 0.f) * cwA +
                       fmaxf(acc2[0][t][3] + b1v, 0.f) * cwB +
                       fmaxf(acc2[1][t][1] + b1v, 0.f) * cwC +
                       fmaxf(acc2[1][t][3] + b1v, 0.f) * cwD;
#pragma unroll
            for (int o = 4; o <= 16; o <<= 1) {
                p0 += __shfl_xor_sync(0xffffffffu, p0, o);
                p1 += __shfl_xor_sync(0xffffffffu, p1, o);
            }
            if (lane < 4) {
                atomicAdd(&pool[c0], p0);
                atomicAdd(&pool[c0 + 1], p1);
            }
        }
    }
    __syncthreads();
    if (tid < 64) pool[tid] = fmaxf(pool[tid], 0.f);
    __syncthreads();

    // ---- final fc ----
    if (tid < C_OUT) {
        float s = __ldg(fc_b + tid);
#pragma unroll 8
        for (int h = 0; h < H_DIM; h++)
            s = fmaf(pool[h], __ldg(fc_w + h * C_OUT + tid), s);
        out[b * C_OUT + tid] = s;
    }
}

// ===========================================================================
extern "C" void kernel_launch(void* const* d_in, const int* in_sizes, int n_in,
                              void* d_out, int out_size) {
    const float* x      = (const float*)d_in[0];
    const float* edge_w = (const float*)d_in[1];
    const float* lin_w  = (const float*)d_in[2];
    const float* lin_b  = (const float*)d_in[3];
    const float* conv_w = (const float*)d_in[4];
    const float* conv_b = (const float*)d_in[5];
    const float* fc_w   = (const float*)d_in[6];
    const float* fc_b   = (const float*)d_in[7];
    float* out = (float*)d_out;

    cudaFuncSetAttribute(fused_mma, cudaFuncAttributeMaxDynamicSharedMemorySize,
                         SM_TOTAL);

    build_Ahat<<<N_NODES, 128>>>(edge_w);
    build_A2<<<N_NODES, 128>>>();
    build_frags<<<24, 256>>>(lin_w);
    fused_mma<<<BATCH, 256, SM_TOTAL>>>(x, lin_b, conv_w, conv_b, fc_w, fc_b, out);
}